// round 14
// baseline (speedup 1.0000x reference)
#include <cuda_runtime.h>
#include <math.h>

#define N_NODES 150000
#define D 100
#define T_STEPS 16
#define E_EDGES 262144          // 2^18
#define E_SHIFT 18
#define S_SEEDS 4096
#define K_CAND 9
#define G4 400                  // 4*D gates
#define KDIM 200                // concat(x, h_prev)
#define LDP 68                  // padded smem stride for GEMM tiles
#define SMEM_GEMM (2 * KDIM * LDP * (int)sizeof(float))

#define NT (T_STEPS * N_NODES)          // 2,400,000 bins
#define TE (T_STEPS * E_EDGES)          // 4,194,304 edges
#define SCAN_ELEMS 1024                 // elems per scan block (256 thr x int4)
#define NBLK ((NT + SCAN_ELEMS - 1) / SCAN_ELEMS)  // 2344

// ---------------- persistent device state (no allocation allowed) ----------
__device__ float g_emb[N_NODES * D];            // ping buffer (60 MB)
__device__ float g_emb2[N_NODES * D];           // pong buffer (60 MB)
__device__ float g_c[N_NODES * D];              // lazy cell state (60 MB)
__device__ int   g_cstamp[N_NODES];             // 0 => c row == cx row (zero-init)
__device__ float g_A[S_SEEDS * KDIM];           // snapshot [x | h_prev] per seed
__device__ float g_cprev[S_SEEDS * D];          // c[seed] snapshot
__device__ float g_W[G4 * KDIM];                // [W_ih | W_hh]
__device__ float g_b[G4];                       // b_ih + b_hh
__device__ float g_user[T_STEPS * S_SEEDS * D]; // h history (26 MB)

__device__ int g_hist[NT];          // per (t,node) in-degree (zero-init; cleared in scan)
__device__ int g_start[NT + 4];     // exclusive scan (+ sentinel at [NT])
__device__ int g_cur[NT];           // fill cursors
__device__ unsigned g_stat[NBLK];   // decoupled-lookback status (flag<<30 | value)
__device__ unsigned g_ticket;       // scan block ticket
__device__ int g_epack[TE];         // src | (cat<<18), grouped by (t,dst)

// ---------------- helpers ---------------------------------------------------
__device__ __forceinline__ float sigf(float x) {
    return 1.0f / (1.0f + expf(-x));
}

// ---------------- CSR build -------------------------------------------------
// histogram; also reset scan status/ticket for this call
__global__ void k_hist(const int* __restrict__ dst) {
    int ti = blockIdx.x * blockDim.x + threadIdx.x;
    if (ti < NBLK) g_stat[ti] = 0u;
    if (ti == NBLK) g_ticket = 0u;
    if (ti >= TE) return;
    int bin = (ti >> E_SHIFT) * N_NODES + dst[ti];
    atomicAdd(&g_hist[bin], 1);
}

// single-pass exclusive scan with decoupled lookback.
// Each block: 256 threads x int4 = 1024 elems. Reads AND zeroes g_hist.
__global__ void __launch_bounds__(256) k_scan() {
    __shared__ int wsum[8];
    __shared__ int s_bid;
    __shared__ int s_run;
    int tid = threadIdx.x;
    if (tid == 0) s_bid = (int)atomicAdd(&g_ticket, 1u);
    __syncthreads();
    int b = s_bid;
    int lane = tid & 31, w = tid >> 5;
    int gi = b * 256 + tid;                 // int4 index
    int4 v = make_int4(0, 0, 0, 0);
    if (gi < NT / 4) {
        v = ((int4*)g_hist)[gi];
        ((int4*)g_hist)[gi] = make_int4(0, 0, 0, 0);  // pre-clear for next call
    }
    int s = v.x + v.y + v.z + v.w;
    int inc = s;
#pragma unroll
    for (int off = 1; off < 32; off <<= 1) {
        int x = __shfl_up_sync(0xffffffffu, inc, off);
        if (lane >= off) inc += x;
    }
    if (lane == 31) wsum[w] = inc;
    __syncthreads();
    if (w == 0) {
        int ws = (lane < 8) ? wsum[lane] : 0;
#pragma unroll
        for (int off = 1; off < 8; off <<= 1) {
            int x = __shfl_up_sync(0xffffffffu, ws, off);
            if (lane >= off) ws += x;
        }
        if (lane < 8) wsum[lane] = ws;
    }
    __syncthreads();

    // decoupled lookback by thread 0 (single packed word: flag<<30 | value)
    if (tid == 0) {
        unsigned total = (unsigned)wsum[7];
        int run = 0;
        if (b == 0) {
            atomicExch(&g_stat[0], (2u << 30) | total);
        } else {
            atomicExch(&g_stat[b], (1u << 30) | total);
            int j = b - 1;
            while (true) {
                unsigned st;
                do { st = atomicAdd(&g_stat[j], 0u); } while ((st >> 30) == 0u);
                run += (int)(st & 0x3FFFFFFFu);
                if ((st >> 30) == 2u) break;
                j--;
            }
            atomicExch(&g_stat[b], (2u << 30) | ((unsigned)run + total));
        }
        s_run = run;
    }
    __syncthreads();

    int base = inc - s + (w > 0 ? wsum[w - 1] : 0) + s_run;
    if (gi < NT / 4) {
        int4 o;
        o.x = base;
        o.y = base + v.x;
        o.z = o.y + v.y;
        o.w = o.z + v.z;
        ((int4*)g_start)[gi] = o;
        ((int4*)g_cur)[gi] = o;
    }
    if (b == NBLK - 1 && tid == 0) g_start[NT] = TE;
}

// bucket fill: place each edge into its (t,dst) segment
__global__ void k_fill(const int* __restrict__ src,
                       const int* __restrict__ dst,
                       const int* __restrict__ cat) {
    int ti = blockIdx.x * blockDim.x + threadIdx.x;
    if (ti >= TE) return;
    int bin = (ti >> E_SHIFT) * N_NODES + dst[ti];
    int pos = atomicAdd(&g_cur[bin], 1);
    g_epack[pos] = src[ti] | (cat[ti] << 18);
}

// ---------------- weight prep ------------------------------------------------
__global__ void k_wprep(const float* __restrict__ W_ih,
                        const float* __restrict__ W_hh,
                        const float* __restrict__ b_ih,
                        const float* __restrict__ b_hh) {
    int idx = blockIdx.x * blockDim.x + threadIdx.x;
    if (idx < G4 * KDIM) {
        int g = idx / KDIM, k = idx - g * KDIM;
        g_W[idx] = (k < D) ? W_ih[g * D + k] : W_hh[g * D + (k - D)];
    }
    if (idx < G4) g_b[idx] = b_ih[idx] + b_hh[idx];
}

// ---------------- per-step aggregation (gather, no atomics) ------------------
// nb[n] = ob[n] + (sum_{e: dst=n} ob[src_e] * rel[cat_e]) / deg
__global__ void __launch_bounds__(256) k_agg(int t,
                                             const float* __restrict__ ob,
                                             float* __restrict__ nb,
                                             const float* __restrict__ rel) {
    int n = blockIdx.x * 8 + (threadIdx.x >> 5);
    if (n >= N_NODES) return;
    int lane = threadIdx.x & 31;
    int bin = t * N_NODES + n;
    int s0 = __ldg(&g_start[bin]);
    int s1 = __ldg(&g_start[bin + 1]);
    int deg = s1 - s0;

    float4 acc = make_float4(0.f, 0.f, 0.f, 0.f);
    for (int j0 = 0; j0 < deg; j0 += 32) {
        int m = deg - j0;
        if (m > 32) m = 32;
        int pk = (lane < m) ? __ldg(&g_epack[s0 + j0 + lane]) : 0;
#pragma unroll 4
        for (int j = 0; j < m; j++) {
            int p = __shfl_sync(0xffffffffu, pk, j);
            if (lane < D / 4) {
                int s = p & 0x3FFFF;
                int c = p >> 18;
                float4 a = __ldg(((const float4*)ob) + s * (D / 4) + lane);
                float4 r = __ldg(((const float4*)rel) + c * (D / 4) + lane);
                acc.x = fmaf(a.x, r.x, acc.x);
                acc.y = fmaf(a.y, r.y, acc.y);
                acc.z = fmaf(a.z, r.z, acc.z);
                acc.w = fmaf(a.w, r.w, acc.w);
            }
        }
    }
    if (lane < D / 4) {
        float4 e = __ldg(((const float4*)ob) + n * (D / 4) + lane);
        if (deg > 0) {
            float invd = 1.0f / (float)deg;
            e.x += acc.x * invd;
            e.y += acc.y * invd;
            e.z += acc.z * invd;
            e.w += acc.w * invd;
        }
        ((float4*)nb)[n * (D / 4) + lane] = e;
    }
}

// ---------------- per-step snapshot (race-free vs duplicate seeds) -----------
// g_A[s] = [ x = nb[seed_s] | h_prev = ob[seed_s] ], g_cprev[s] = c_prev (lazy)
__global__ void k_xsnap(const float* __restrict__ ob,
                        const float* __restrict__ nb,
                        const float* __restrict__ cx,
                        const int* __restrict__ seeds) {
    int idx = blockIdx.x * blockDim.x + threadIdx.x;
    int s = idx / (D / 4), q = idx - s * (D / 4);
    if (s >= S_SEEDS) return;
    int node = seeds[s];
    float4 xv = __ldg(((const float4*)nb) + node * (D / 4) + q);
    float4 hv = __ldg(((const float4*)ob) + node * (D / 4) + q);
    ((float4*)(g_A + s * KDIM))[q] = xv;
    ((float4*)(g_A + s * KDIM + D))[q] = hv;
    float4 cv = g_cstamp[node]
        ? ((const float4*)(g_c + node * D))[q]
        : __ldg(((const float4*)cx) + node * (D / 4) + q);
    ((float4*)(g_cprev + s * D))[q] = cv;
}

// ---------------- fused LSTM GEMM + pointwise --------------------------------
// Block: 64 seeds x 16 j's x 4 gates. B smem columns packed c = jj*4 + strip so
// a thread's (i,f,g,o) for one j is a single LDS.128. Epilogue applies the LSTM
// nonlinearity and scatters h/c/user directly (duplicate-seed writes identical).
__global__ void __launch_bounds__(128) k_gemmpoint(float* __restrict__ nb,
                                                   const int* __restrict__ seeds,
                                                   int t) {
    extern __shared__ float sm[];
    float* As = sm;                 // [KDIM][LDP]
    float* Bs = sm + KDIM * LDP;    // [KDIM][LDP]
    __shared__ int sseed[64];

    int tid = threadIdx.x;
    int s0 = blockIdx.x * 64;
    int j0 = blockIdx.y * 16;

    if (tid < 64) sseed[tid] = seeds[s0 + tid];

    // A tile: contiguous snapshot rows (64 x 200), transposed into smem
    for (int i = tid; i < 64 * (KDIM / 4); i += 128) {
        int r = i / (KDIM / 4), q = i - r * (KDIM / 4);
        float4 v = ((const float4*)(g_A + (s0 + r) * KDIM))[q];
        int k = q * 4;
        As[(k + 0) * LDP + r] = v.x;
        As[(k + 1) * LDP + r] = v.y;
        As[(k + 2) * LDP + r] = v.z;
        As[(k + 3) * LDP + r] = v.w;
    }
    // B tile: column c = jj*4 + strip holds W row (strip*100 + j0 + jj)
    for (int i = tid; i < 64 * (KDIM / 4); i += 128) {
        int cidx = i / (KDIM / 4), q = i - cidx * (KDIM / 4);
        int jj = cidx >> 2, strip = cidx & 3;
        int j = j0 + jj;
        float4 v = (j < D) ? *(const float4*)(g_W + (strip * D + j) * KDIM + q * 4)
                           : make_float4(0.f, 0.f, 0.f, 0.f);
        int k = q * 4;
        Bs[(k + 0) * LDP + cidx] = v.x;
        Bs[(k + 1) * LDP + cidx] = v.y;
        Bs[(k + 2) * LDP + cidx] = v.z;
        Bs[(k + 3) * LDP + cidx] = v.w;
    }
    __syncthreads();

    int tx = tid & 15;      // jj
    int ty = tid >> 4;      // seed group (8 seeds)

    float acc[8][4];
#pragma unroll
    for (int i = 0; i < 8; i++)
#pragma unroll
        for (int j = 0; j < 4; j++) acc[i][j] = 0.0f;

#pragma unroll 4
    for (int k = 0; k < KDIM; k++) {
        float4 b4 = *(const float4*)(Bs + k * LDP + tx * 4);  // i,f,g,o @ j
        float4 a0 = *(const float4*)(As + k * LDP + ty * 8);
        float4 a1 = *(const float4*)(As + k * LDP + ty * 8 + 4);
        float av[8] = {a0.x, a0.y, a0.z, a0.w, a1.x, a1.y, a1.z, a1.w};
        float bv[4] = {b4.x, b4.y, b4.z, b4.w};
#pragma unroll
        for (int i = 0; i < 8; i++)
#pragma unroll
            for (int j = 0; j < 4; j++) acc[i][j] += av[i] * bv[j];
    }

    // epilogue: LSTM pointwise + scatter
    int j = j0 + tx;
    if (j < D) {
        float bi = __ldg(&g_b[j]);
        float bf = __ldg(&g_b[D + j]);
        float bg = __ldg(&g_b[2 * D + j]);
        float bo = __ldg(&g_b[3 * D + j]);
#pragma unroll
        for (int i = 0; i < 8; i++) {
            int sr = ty * 8 + i;
            int node = sseed[sr];
            float cp = g_cprev[(s0 + sr) * D + j];
            float ig = acc[i][0] + bi;
            float fg = acc[i][1] + bf;
            float gg = acc[i][2] + bg;
            float og = acc[i][3] + bo;
            float cn = sigf(fg) * cp + sigf(ig) * tanhf(gg);
            float hn = sigf(og) * tanhf(cn);
            g_c[node * D + j] = cn;
            nb[node * D + j] = hn;
            g_user[((t * S_SEEDS) + s0 + sr) * D + j] = hn;
        }
    }
    if (blockIdx.y == 0 && tx == 0) {
#pragma unroll
        for (int i = 0; i < 8; i++) g_cstamp[sseed[ty * 8 + i]] = 1;
    }
}

// ---------------- scoring ------------------------------------------------------
__global__ void k_score(const float* __restrict__ emb_final,
                        const int* __restrict__ cand,
                        float* __restrict__ out) {
    __shared__ float u[D];
    int n = blockIdx.x;
    int tid = threadIdx.x;
    if (tid < D) u[tid] = g_user[n * D + tid];
    __syncthreads();
    int w = tid >> 5, lane = tid & 31;
    if (w >= K_CAND) return;
    int cidx = cand[n * K_CAND + w];
    const float* cr = emb_final + cidx * D;
    float sum = 0.0f;
    for (int j = lane; j < D; j += 32) sum += u[j] * cr[j];
#pragma unroll
    for (int o = 16; o; o >>= 1) sum += __shfl_down_sync(0xffffffffu, sum, o);
    if (lane == 0) out[n * K_CAND + w] = sum;
}

// tail: restore stamp invariants for next graph replay
__global__ void k_clean(const int* __restrict__ seeds) {
    int i = blockIdx.x * blockDim.x + threadIdx.x;
    if (i < T_STEPS * S_SEEDS) g_cstamp[seeds[i]] = 0;
}

// ---------------- host ------------------------------------------------------
extern "C" void kernel_launch(void* const* d_in, const int* in_sizes, int n_in,
                              void* d_out, int out_size) {
    const float* node_emb = (const float*)d_in[0];
    const float* cx       = (const float*)d_in[1];
    const float* rel      = (const float*)d_in[2];
    const float* W_ih     = (const float*)d_in[3];
    const float* W_hh     = (const float*)d_in[4];
    const float* b_ih     = (const float*)d_in[5];
    const float* b_hh     = (const float*)d_in[6];
    const int* src   = (const int*)d_in[7];
    const int* dst   = (const int*)d_in[8];
    const int* cat   = (const int*)d_in[9];
    const int* seeds = (const int*)d_in[10];
    const int* cand  = (const int*)d_in[11];
    float* out = (float*)d_out;

    (void)in_sizes; (void)n_in; (void)out_size;

    cudaFuncSetAttribute(k_gemmpoint,
                         cudaFuncAttributeMaxDynamicSharedMemorySize, SMEM_GEMM);

    float *p_emb = nullptr, *p_emb2 = nullptr;
    cudaGetSymbolAddress((void**)&p_emb, g_emb);
    cudaGetSymbolAddress((void**)&p_emb2, g_emb2);

    // CSR build (3 kernels), then step 0's k_agg is the 4th launch (profiled)
    k_hist<<<(TE + 255) / 256, 256>>>(dst);
    k_scan<<<NBLK, 256>>>();
    k_fill<<<(TE + 255) / 256, 256>>>(src, dst, cat);

    k_agg<<<(N_NODES + 7) / 8, 256>>>(0, node_emb, p_emb, rel);      // 4th
    k_wprep<<<(G4 * KDIM + 255) / 256, 256>>>(W_ih, W_hh, b_ih, b_hh);
    k_xsnap<<<(S_SEEDS * (D / 4) + 255) / 256, 256>>>(node_emb, p_emb, cx, seeds);
    k_gemmpoint<<<dim3(S_SEEDS / 64, 7), 128, SMEM_GEMM>>>(p_emb, seeds, 0);

    for (int t = 1; t < T_STEPS; t++) {
        const float* ob = (t & 1) ? p_emb : p_emb2;
        float* nb = (t & 1) ? p_emb2 : p_emb;
        const int* seeds_t = seeds + t * S_SEEDS;
        k_agg<<<(N_NODES + 7) / 8, 256>>>(t, ob, nb, rel);
        k_xsnap<<<(S_SEEDS * (D / 4) + 255) / 256, 256>>>(ob, nb, cx, seeds_t);
        k_gemmpoint<<<dim3(S_SEEDS / 64, 7), 128, SMEM_GEMM>>>(nb, seeds_t, t);
    }

    // final embeddings: t=15 wrote p_emb2
    k_score<<<T_STEPS * S_SEEDS, 288>>>(p_emb2, cand, out);
    k_clean<<<(T_STEPS * S_SEEDS + 255) / 256, 256>>>(seeds);
}

// round 15
// speedup vs baseline: 1.3108x; 1.3108x over previous
#include <cuda_runtime.h>
#include <math.h>

#define N_NODES 150000
#define D 100
#define T_STEPS 16
#define E_EDGES 262144          // 2^18
#define E_SHIFT 18
#define S_SEEDS 4096
#define K_CAND 9
#define G4 400                  // 4*D gates
#define KDIM 200                // concat(x, h_prev)
#define KC 100                  // K-chunk for GEMM smem
#define LDP 68                  // padded smem stride for GEMM tiles
#define SMEM_GEMM (2 * KC * LDP * (int)sizeof(float))   // 54.4 KB

#define NT (T_STEPS * N_NODES)          // 2,400,000 bins
#define TE (T_STEPS * E_EDGES)          // 4,194,304 edges
#define SCAN_ELEMS 1024                 // elems per scan block (256 thr x int4)
#define NBLK ((NT + SCAN_ELEMS - 1) / SCAN_ELEMS)  // 2344

// ---------------- persistent device state (no allocation allowed) ----------
__device__ float g_emb[N_NODES * D];            // ping buffer (60 MB)
__device__ float g_emb2[N_NODES * D];           // pong buffer (60 MB)
__device__ float g_c[N_NODES * D];              // lazy cell state (60 MB)
__device__ int   g_cstamp[N_NODES];             // 0 => c row == cx row (zero-init)
__device__ float g_A[S_SEEDS * KDIM];           // snapshot [x | h_prev] per seed
__device__ float g_cprev[S_SEEDS * D];          // c[seed] snapshot
__device__ float g_W[G4 * KDIM];                // [W_ih | W_hh]
__device__ float g_b[G4];                       // b_ih + b_hh
__device__ float g_user[T_STEPS * S_SEEDS * D]; // h history (26 MB)

__device__ int g_hist[NT];          // per (t,node) in-degree (zero-init; cleared in scan)
__device__ int g_start[NT + 4];     // exclusive scan (+ sentinel at [NT])
__device__ int g_cur[NT];           // fill cursors
__device__ unsigned g_stat[NBLK];   // decoupled-lookback status (flag<<30 | value)
__device__ unsigned g_ticket;       // scan block ticket
__device__ int g_epack[TE];         // src | (cat<<18), grouped by (t,dst)

// ---------------- helpers ---------------------------------------------------
__device__ __forceinline__ float sigf(float x) {
    return 1.0f / (1.0f + expf(-x));
}

// ---------------- CSR build -------------------------------------------------
__global__ void k_hist(const int* __restrict__ dst) {
    int ti = blockIdx.x * blockDim.x + threadIdx.x;
    if (ti < NBLK) g_stat[ti] = 0u;
    if (ti == NBLK) g_ticket = 0u;
    if (ti >= TE) return;
    int bin = (ti >> E_SHIFT) * N_NODES + dst[ti];
    atomicAdd(&g_hist[bin], 1);
}

// single-pass exclusive scan with decoupled lookback; reads AND zeroes g_hist.
__global__ void __launch_bounds__(256) k_scan() {
    __shared__ int wsum[8];
    __shared__ int s_bid;
    __shared__ int s_run;
    int tid = threadIdx.x;
    if (tid == 0) s_bid = (int)atomicAdd(&g_ticket, 1u);
    __syncthreads();
    int b = s_bid;
    int lane = tid & 31, w = tid >> 5;
    int gi = b * 256 + tid;                 // int4 index
    int4 v = make_int4(0, 0, 0, 0);
    if (gi < NT / 4) {
        v = ((int4*)g_hist)[gi];
        ((int4*)g_hist)[gi] = make_int4(0, 0, 0, 0);
    }
    int s = v.x + v.y + v.z + v.w;
    int inc = s;
#pragma unroll
    for (int off = 1; off < 32; off <<= 1) {
        int x = __shfl_up_sync(0xffffffffu, inc, off);
        if (lane >= off) inc += x;
    }
    if (lane == 31) wsum[w] = inc;
    __syncthreads();
    if (w == 0) {
        int ws = (lane < 8) ? wsum[lane] : 0;
#pragma unroll
        for (int off = 1; off < 8; off <<= 1) {
            int x = __shfl_up_sync(0xffffffffu, ws, off);
            if (lane >= off) ws += x;
        }
        if (lane < 8) wsum[lane] = ws;
    }
    __syncthreads();

    if (tid == 0) {
        unsigned total = (unsigned)wsum[7];
        int run = 0;
        if (b == 0) {
            atomicExch(&g_stat[0], (2u << 30) | total);
        } else {
            atomicExch(&g_stat[b], (1u << 30) | total);
            int j = b - 1;
            while (true) {
                unsigned st;
                do { st = atomicAdd(&g_stat[j], 0u); } while ((st >> 30) == 0u);
                run += (int)(st & 0x3FFFFFFFu);
                if ((st >> 30) == 2u) break;
                j--;
            }
            atomicExch(&g_stat[b], (2u << 30) | ((unsigned)run + total));
        }
        s_run = run;
    }
    __syncthreads();

    int base = inc - s + (w > 0 ? wsum[w - 1] : 0) + s_run;
    if (gi < NT / 4) {
        int4 o;
        o.x = base;
        o.y = base + v.x;
        o.z = o.y + v.y;
        o.w = o.z + v.z;
        ((int4*)g_start)[gi] = o;
        ((int4*)g_cur)[gi] = o;
    }
    if (b == NBLK - 1 && tid == 0) g_start[NT] = TE;
}

// bucket fill: place each edge into its (t,dst) segment
__global__ void k_fill(const int* __restrict__ src,
                       const int* __restrict__ dst,
                       const int* __restrict__ cat) {
    int ti = blockIdx.x * blockDim.x + threadIdx.x;
    if (ti >= TE) return;
    int bin = (ti >> E_SHIFT) * N_NODES + dst[ti];
    int pos = atomicAdd(&g_cur[bin], 1);
    g_epack[pos] = src[ti] | (cat[ti] << 18);
}

// ---------------- weight prep ------------------------------------------------
__global__ void k_wprep(const float* __restrict__ W_ih,
                        const float* __restrict__ W_hh,
                        const float* __restrict__ b_ih,
                        const float* __restrict__ b_hh) {
    int idx = blockIdx.x * blockDim.x + threadIdx.x;
    if (idx < G4 * KDIM) {
        int g = idx / KDIM, k = idx - g * KDIM;
        g_W[idx] = (k < D) ? W_ih[g * D + k] : W_hh[g * D + (k - D)];
    }
    if (idx < G4) g_b[idx] = b_ih[idx] + b_hh[idx];
}

// ---------------- per-step aggregation (gather, no atomics) ------------------
// Two nodes per warp with interleaved edge streams for MLP.
// nb[n] = ob[n] + (sum_{e: dst=n} ob[src_e] * rel[cat_e]) / deg
__global__ void __launch_bounds__(256) k_agg(int t,
                                             const float* __restrict__ ob,
                                             float* __restrict__ nb,
                                             const float* __restrict__ rel) {
    int pair = blockIdx.x * 8 + (threadIdx.x >> 5);
    int n0 = pair * 2;
    if (n0 >= N_NODES) return;
    int lane = threadIdx.x & 31;
    int bin = t * N_NODES + n0;

    // one coalesced access: starts for nodes n0, n0+1 and the end sentinel
    int sv = (lane < 3) ? __ldg(&g_start[bin + lane]) : 0;
    int s0 = __shfl_sync(0xffffffffu, sv, 0);
    int s1 = __shfl_sync(0xffffffffu, sv, 1);
    int s2 = __shfl_sync(0xffffffffu, sv, 2);
    int deg0 = s1 - s0, deg1 = s2 - s1;
    int total = s2 - s0;

    // prefetch the combined contiguous epack range (one coalesced load)
    int pk = (lane < total) ? __ldg(&g_epack[s0 + lane]) : 0;

    // residual rows issued early (independent of edge chain)
    float4 e0 = make_float4(0.f, 0.f, 0.f, 0.f), e1 = e0;
    if (lane < D / 4) {
        e0 = __ldg(((const float4*)ob) + n0 * (D / 4) + lane);
        e1 = __ldg(((const float4*)ob) + (n0 + 1) * (D / 4) + lane);
    }

    float4 acc0 = make_float4(0.f, 0.f, 0.f, 0.f), acc1 = acc0;
    int dmax = deg0 > deg1 ? deg0 : deg1;
#pragma unroll 2
    for (int j = 0; j < dmax; j++) {
        if (j < deg0) {
            int p = j;
            int pkj = (p < 32) ? __shfl_sync(0xffffffffu, pk, p)
                               : __ldg(&g_epack[s0 + p]);
            if (lane < D / 4) {
                int s = pkj & 0x3FFFF, c = pkj >> 18;
                float4 a = __ldg(((const float4*)ob) + s * (D / 4) + lane);
                float4 r = __ldg(((const float4*)rel) + c * (D / 4) + lane);
                acc0.x = fmaf(a.x, r.x, acc0.x);
                acc0.y = fmaf(a.y, r.y, acc0.y);
                acc0.z = fmaf(a.z, r.z, acc0.z);
                acc0.w = fmaf(a.w, r.w, acc0.w);
            }
        }
        if (j < deg1) {
            int p = (s1 - s0) + j;
            int pkj = (p < 32) ? __shfl_sync(0xffffffffu, pk, p)
                               : __ldg(&g_epack[s0 + p]);
            if (lane < D / 4) {
                int s = pkj & 0x3FFFF, c = pkj >> 18;
                float4 a = __ldg(((const float4*)ob) + s * (D / 4) + lane);
                float4 r = __ldg(((const float4*)rel) + c * (D / 4) + lane);
                acc1.x = fmaf(a.x, r.x, acc1.x);
                acc1.y = fmaf(a.y, r.y, acc1.y);
                acc1.z = fmaf(a.z, r.z, acc1.z);
                acc1.w = fmaf(a.w, r.w, acc1.w);
            }
        }
    }

    if (lane < D / 4) {
        if (deg0 > 0) {
            float inv = 1.0f / (float)deg0;
            e0.x += acc0.x * inv; e0.y += acc0.y * inv;
            e0.z += acc0.z * inv; e0.w += acc0.w * inv;
        }
        ((float4*)nb)[n0 * (D / 4) + lane] = e0;
        if (deg1 > 0) {
            float inv = 1.0f / (float)deg1;
            e1.x += acc1.x * inv; e1.y += acc1.y * inv;
            e1.z += acc1.z * inv; e1.w += acc1.w * inv;
        }
        ((float4*)nb)[(n0 + 1) * (D / 4) + lane] = e1;
    }
}

// ---------------- per-step snapshot (race-free vs duplicate seeds) -----------
__global__ void k_xsnap(const float* __restrict__ ob,
                        const float* __restrict__ nb,
                        const float* __restrict__ cx,
                        const int* __restrict__ seeds) {
    int idx = blockIdx.x * blockDim.x + threadIdx.x;
    int s = idx / (D / 4), q = idx - s * (D / 4);
    if (s >= S_SEEDS) return;
    int node = seeds[s];
    float4 xv = __ldg(((const float4*)nb) + node * (D / 4) + q);
    float4 hv = __ldg(((const float4*)ob) + node * (D / 4) + q);
    ((float4*)(g_A + s * KDIM))[q] = xv;
    ((float4*)(g_A + s * KDIM + D))[q] = hv;
    float4 cv = g_cstamp[node]
        ? ((const float4*)(g_c + node * D))[q]
        : __ldg(((const float4*)cx) + node * (D / 4) + q);
    ((float4*)(g_cprev + s * D))[q] = cv;
}

// ---------------- fused LSTM GEMM + pointwise --------------------------------
// Block: 64 seeds x 16 j's x 4 gates, K processed in 2 chunks of 100 so smem
// is 54.4 KB -> 4 blocks/SM. B smem columns packed c = jj*4 + strip so a
// thread's (i,f,g,o) for one j is a single LDS.128.
__global__ void __launch_bounds__(128) k_gemmpoint(float* __restrict__ nb,
                                                   const int* __restrict__ seeds,
                                                   int t) {
    extern __shared__ float sm[];
    float* As = sm;               // [KC][LDP]
    float* Bs = sm + KC * LDP;    // [KC][LDP]
    __shared__ int sseed[64];

    int tid = threadIdx.x;
    int s0 = blockIdx.x * 64;
    int j0 = blockIdx.y * 16;

    if (tid < 64) sseed[tid] = seeds[s0 + tid];

    int tx = tid & 15;      // jj
    int ty = tid >> 4;      // seed group (8 seeds)

    float acc[8][4];
#pragma unroll
    for (int i = 0; i < 8; i++)
#pragma unroll
        for (int j = 0; j < 4; j++) acc[i][j] = 0.0f;

    for (int kc = 0; kc < 2; kc++) {
        __syncthreads();
        // A chunk: rows = seeds, k in [kc*100, kc*100+100)
        for (int i = tid; i < 64 * (KC / 4); i += 128) {
            int r = i / (KC / 4), q = i - r * (KC / 4);
            float4 v = ((const float4*)(g_A + (s0 + r) * KDIM + kc * KC))[q];
            int k = q * 4;
            As[(k + 0) * LDP + r] = v.x;
            As[(k + 1) * LDP + r] = v.y;
            As[(k + 2) * LDP + r] = v.z;
            As[(k + 3) * LDP + r] = v.w;
        }
        // B chunk: column c = jj*4 + strip holds W row (strip*100 + j0 + jj)
        for (int i = tid; i < 64 * (KC / 4); i += 128) {
            int cidx = i / (KC / 4), q = i - cidx * (KC / 4);
            int jj = cidx >> 2, strip = cidx & 3;
            int j = j0 + jj;
            float4 v = (j < D)
                ? *(const float4*)(g_W + (strip * D + j) * KDIM + kc * KC + q * 4)
                : make_float4(0.f, 0.f, 0.f, 0.f);
            int k = q * 4;
            Bs[(k + 0) * LDP + cidx] = v.x;
            Bs[(k + 1) * LDP + cidx] = v.y;
            Bs[(k + 2) * LDP + cidx] = v.z;
            Bs[(k + 3) * LDP + cidx] = v.w;
        }
        __syncthreads();

#pragma unroll 4
        for (int k = 0; k < KC; k++) {
            float4 b4 = *(const float4*)(Bs + k * LDP + tx * 4);
            float4 a0 = *(const float4*)(As + k * LDP + ty * 8);
            float4 a1 = *(const float4*)(As + k * LDP + ty * 8 + 4);
            float av[8] = {a0.x, a0.y, a0.z, a0.w, a1.x, a1.y, a1.z, a1.w};
            float bv[4] = {b4.x, b4.y, b4.z, b4.w};
#pragma unroll
            for (int i = 0; i < 8; i++)
#pragma unroll
                for (int j = 0; j < 4; j++) acc[i][j] += av[i] * bv[j];
        }
    }

    // epilogue: LSTM pointwise + scatter (duplicate-seed writes are identical)
    int j = j0 + tx;
    if (j < D) {
        float bi = __ldg(&g_b[j]);
        float bf = __ldg(&g_b[D + j]);
        float bg = __ldg(&g_b[2 * D + j]);
        float bo = __ldg(&g_b[3 * D + j]);
#pragma unroll
        for (int i = 0; i < 8; i++) {
            int sr = ty * 8 + i;
            int node = sseed[sr];
            float cp = g_cprev[(s0 + sr) * D + j];
            float ig = acc[i][0] + bi;
            float fg = acc[i][1] + bf;
            float gg = acc[i][2] + bg;
            float og = acc[i][3] + bo;
            float cn = sigf(fg) * cp + sigf(ig) * tanhf(gg);
            float hn = sigf(og) * tanhf(cn);
            g_c[node * D + j] = cn;
            nb[node * D + j] = hn;
            g_user[((t * S_SEEDS) + s0 + sr) * D + j] = hn;
        }
    }
    if (blockIdx.y == 0 && tx == 0) {
#pragma unroll
        for (int i = 0; i < 8; i++) g_cstamp[sseed[ty * 8 + i]] = 1;
    }
}

// ---------------- scoring ------------------------------------------------------
__global__ void k_score(const float* __restrict__ emb_final,
                        const int* __restrict__ cand,
                        float* __restrict__ out) {
    __shared__ float u[D];
    int n = blockIdx.x;
    int tid = threadIdx.x;
    if (tid < D) u[tid] = g_user[n * D + tid];
    __syncthreads();
    int w = tid >> 5, lane = tid & 31;
    if (w >= K_CAND) return;
    int cidx = cand[n * K_CAND + w];
    const float* cr = emb_final + cidx * D;
    float sum = 0.0f;
    for (int j = lane; j < D; j += 32) sum += u[j] * cr[j];
#pragma unroll
    for (int o = 16; o; o >>= 1) sum += __shfl_down_sync(0xffffffffu, sum, o);
    if (lane == 0) out[n * K_CAND + w] = sum;
}

// tail: restore stamp invariants for next graph replay
__global__ void k_clean(const int* __restrict__ seeds) {
    int i = blockIdx.x * blockDim.x + threadIdx.x;
    if (i < T_STEPS * S_SEEDS) g_cstamp[seeds[i]] = 0;
}

// ---------------- host ------------------------------------------------------
extern "C" void kernel_launch(void* const* d_in, const int* in_sizes, int n_in,
                              void* d_out, int out_size) {
    const float* node_emb = (const float*)d_in[0];
    const float* cx       = (const float*)d_in[1];
    const float* rel      = (const float*)d_in[2];
    const float* W_ih     = (const float*)d_in[3];
    const float* W_hh     = (const float*)d_in[4];
    const float* b_ih     = (const float*)d_in[5];
    const float* b_hh     = (const float*)d_in[6];
    const int* src   = (const int*)d_in[7];
    const int* dst   = (const int*)d_in[8];
    const int* cat   = (const int*)d_in[9];
    const int* seeds = (const int*)d_in[10];
    const int* cand  = (const int*)d_in[11];
    float* out = (float*)d_out;

    (void)in_sizes; (void)n_in; (void)out_size;

    cudaFuncSetAttribute(k_gemmpoint,
                         cudaFuncAttributeMaxDynamicSharedMemorySize, SMEM_GEMM);

    float *p_emb = nullptr, *p_emb2 = nullptr;
    cudaGetSymbolAddress((void**)&p_emb, g_emb);
    cudaGetSymbolAddress((void**)&p_emb2, g_emb2);

    // CSR build
    k_hist<<<(TE + 255) / 256, 256>>>(dst);
    k_scan<<<NBLK, 256>>>();
    k_fill<<<(TE + 255) / 256, 256>>>(src, dst, cat);

    int agg_blocks = (N_NODES / 2 + 7) / 8;
    k_agg<<<agg_blocks, 256>>>(0, node_emb, p_emb, rel);
    k_wprep<<<(G4 * KDIM + 255) / 256, 256>>>(W_ih, W_hh, b_ih, b_hh);
    k_xsnap<<<(S_SEEDS * (D / 4) + 255) / 256, 256>>>(node_emb, p_emb, cx, seeds);
    k_gemmpoint<<<dim3(S_SEEDS / 64, 7), 128, SMEM_GEMM>>>(p_emb, seeds, 0);

    for (int t = 1; t < T_STEPS; t++) {
        const float* ob = (t & 1) ? p_emb : p_emb2;
        float* nb = (t & 1) ? p_emb2 : p_emb;
        const int* seeds_t = seeds + t * S_SEEDS;
        k_agg<<<agg_blocks, 256>>>(t, ob, nb, rel);
        k_xsnap<<<(S_SEEDS * (D / 4) + 255) / 256, 256>>>(ob, nb, cx, seeds_t);
        k_gemmpoint<<<dim3(S_SEEDS / 64, 7), 128, SMEM_GEMM>>>(nb, seeds_t, t);
    }

    // final embeddings: t=15 wrote p_emb2
    k_score<<<T_STEPS * S_SEEDS, 288>>>(p_emb2, cand, out);
    k_clean<<<(T_STEPS * S_SEEDS + 255) / 256, 256>>>(seeds);
}

// round 16
// speedup vs baseline: 1.3110x; 1.0002x over previous
#include <cuda_runtime.h>
#include <math.h>

#define N_NODES 150000
#define D 100
#define T_STEPS 16
#define E_EDGES 262144          // 2^18
#define E_SHIFT 18
#define S_SEEDS 4096
#define K_CAND 9
#define G4 400                  // 4*D gates
#define KDIM 200                // concat(x, h_prev)
#define KC 100                  // K-chunk for GEMM smem
#define LDP 68                  // padded smem stride for GEMM tiles
#define SMEM_GEMM (2 * KC * LDP * (int)sizeof(float))   // 54.4 KB

#define NT (T_STEPS * N_NODES)          // 2,400,000 bins
#define TE (T_STEPS * E_EDGES)          // 4,194,304 edges
#define SCAN_ELEMS 1024                 // elems per scan block (256 thr x int4)
#define NBLK ((NT + SCAN_ELEMS - 1) / SCAN_ELEMS)  // 2344

// ---------------- persistent device state (no allocation allowed) ----------
__device__ float g_emb[N_NODES * D];            // ping buffer (60 MB)
__device__ float g_emb2[N_NODES * D];           // pong buffer (60 MB)
__device__ float g_c[N_NODES * D];              // lazy cell state (60 MB)
__device__ int   g_cstamp[N_NODES];             // 0 => c row == cx row (zero-init)
__device__ float g_A[S_SEEDS * KDIM];           // snapshot [x | h_prev] per seed
__device__ float g_cprev[S_SEEDS * D];          // c[seed] snapshot
__device__ float g_W[G4 * KDIM];                // [W_ih | W_hh]
__device__ float g_b[G4];                       // b_ih + b_hh
__device__ float g_user[T_STEPS * S_SEEDS * D]; // h history (26 MB)

__device__ int g_hist[NT];          // per (t,node) in-degree (zero-init; cleared in scan)
__device__ int g_start[NT + 4];     // exclusive scan (+ sentinel at [NT])
__device__ int g_cur[NT];           // fill cursors
__device__ unsigned g_stat[NBLK];   // decoupled-lookback status (flag<<30 | value)
__device__ unsigned g_ticket;       // scan block ticket
__device__ int g_epack[TE];         // src | (cat<<18), grouped by (t,dst)

// ---------------- helpers ---------------------------------------------------
__device__ __forceinline__ float sigf(float x) {
    return 1.0f / (1.0f + expf(-x));
}

// ---------------- CSR build -------------------------------------------------
__global__ void k_hist(const int* __restrict__ dst) {
    int ti = blockIdx.x * blockDim.x + threadIdx.x;
    if (ti < NBLK) g_stat[ti] = 0u;
    if (ti == NBLK) g_ticket = 0u;
    if (ti >= TE) return;
    int bin = (ti >> E_SHIFT) * N_NODES + dst[ti];
    atomicAdd(&g_hist[bin], 1);
}

// single-pass exclusive scan with decoupled lookback; reads AND zeroes g_hist.
__global__ void __launch_bounds__(256) k_scan() {
    __shared__ int wsum[8];
    __shared__ int s_bid;
    __shared__ int s_run;
    int tid = threadIdx.x;
    if (tid == 0) s_bid = (int)atomicAdd(&g_ticket, 1u);
    __syncthreads();
    int b = s_bid;
    int lane = tid & 31, w = tid >> 5;
    int gi = b * 256 + tid;                 // int4 index
    int4 v = make_int4(0, 0, 0, 0);
    if (gi < NT / 4) {
        v = ((int4*)g_hist)[gi];
        ((int4*)g_hist)[gi] = make_int4(0, 0, 0, 0);
    }
    int s = v.x + v.y + v.z + v.w;
    int inc = s;
#pragma unroll
    for (int off = 1; off < 32; off <<= 1) {
        int x = __shfl_up_sync(0xffffffffu, inc, off);
        if (lane >= off) inc += x;
    }
    if (lane == 31) wsum[w] = inc;
    __syncthreads();
    if (w == 0) {
        int ws = (lane < 8) ? wsum[lane] : 0;
#pragma unroll
        for (int off = 1; off < 8; off <<= 1) {
            int x = __shfl_up_sync(0xffffffffu, ws, off);
            if (lane >= off) ws += x;
        }
        if (lane < 8) wsum[lane] = ws;
    }
    __syncthreads();

    if (tid == 0) {
        unsigned total = (unsigned)wsum[7];
        int run = 0;
        if (b == 0) {
            atomicExch(&g_stat[0], (2u << 30) | total);
        } else {
            atomicExch(&g_stat[b], (1u << 30) | total);
            int j = b - 1;
            while (true) {
                unsigned st;
                do { st = atomicAdd(&g_stat[j], 0u); } while ((st >> 30) == 0u);
                run += (int)(st & 0x3FFFFFFFu);
                if ((st >> 30) == 2u) break;
                j--;
            }
            atomicExch(&g_stat[b], (2u << 30) | ((unsigned)run + total));
        }
        s_run = run;
    }
    __syncthreads();

    int base = inc - s + (w > 0 ? wsum[w - 1] : 0) + s_run;
    if (gi < NT / 4) {
        int4 o;
        o.x = base;
        o.y = base + v.x;
        o.z = o.y + v.y;
        o.w = o.z + v.z;
        ((int4*)g_start)[gi] = o;
        ((int4*)g_cur)[gi] = o;
    }
    if (b == NBLK - 1 && tid == 0) g_start[NT] = TE;
}

// bucket fill: place each edge into its (t,dst) segment
__global__ void k_fill(const int* __restrict__ src,
                       const int* __restrict__ dst,
                       const int* __restrict__ cat) {
    int ti = blockIdx.x * blockDim.x + threadIdx.x;
    if (ti >= TE) return;
    int bin = (ti >> E_SHIFT) * N_NODES + dst[ti];
    int pos = atomicAdd(&g_cur[bin], 1);
    g_epack[pos] = src[ti] | (cat[ti] << 18);
}

// ---------------- weight prep ------------------------------------------------
__global__ void k_wprep(const float* __restrict__ W_ih,
                        const float* __restrict__ W_hh,
                        const float* __restrict__ b_ih,
                        const float* __restrict__ b_hh) {
    int idx = blockIdx.x * blockDim.x + threadIdx.x;
    if (idx < G4 * KDIM) {
        int g = idx / KDIM, k = idx - g * KDIM;
        g_W[idx] = (k < D) ? W_ih[g * D + k] : W_hh[g * D + (k - D)];
    }
    if (idx < G4) g_b[idx] = b_ih[idx] + b_hh[idx];
}

// ---------------- per-step aggregation (gather, no atomics) ------------------
// Two nodes per warp with interleaved edge streams for MLP.
// nb[n] = ob[n] + (sum_{e: dst=n} ob[src_e] * rel[cat_e]) / deg
__global__ void __launch_bounds__(256) k_agg(int t,
                                             const float* __restrict__ ob,
                                             float* __restrict__ nb,
                                             const float* __restrict__ rel) {
    int pair = blockIdx.x * 8 + (threadIdx.x >> 5);
    int n0 = pair * 2;
    if (n0 >= N_NODES) return;
    int lane = threadIdx.x & 31;
    int bin = t * N_NODES + n0;

    // one coalesced access: starts for nodes n0, n0+1 and the end sentinel
    int sv = (lane < 3) ? __ldg(&g_start[bin + lane]) : 0;
    int s0 = __shfl_sync(0xffffffffu, sv, 0);
    int s1 = __shfl_sync(0xffffffffu, sv, 1);
    int s2 = __shfl_sync(0xffffffffu, sv, 2);
    int deg0 = s1 - s0, deg1 = s2 - s1;
    int total = s2 - s0;

    // prefetch the combined contiguous epack range (one coalesced load)
    int pk = (lane < total) ? __ldg(&g_epack[s0 + lane]) : 0;

    // residual rows issued early (independent of edge chain)
    float4 e0 = make_float4(0.f, 0.f, 0.f, 0.f), e1 = e0;
    if (lane < D / 4) {
        e0 = __ldg(((const float4*)ob) + n0 * (D / 4) + lane);
        e1 = __ldg(((const float4*)ob) + (n0 + 1) * (D / 4) + lane);
    }

    float4 acc0 = make_float4(0.f, 0.f, 0.f, 0.f), acc1 = acc0;
    int dmax = deg0 > deg1 ? deg0 : deg1;
#pragma unroll 2
    for (int j = 0; j < dmax; j++) {
        if (j < deg0) {
            int p = j;
            int pkj = (p < 32) ? __shfl_sync(0xffffffffu, pk, p)
                               : __ldg(&g_epack[s0 + p]);
            if (lane < D / 4) {
                int s = pkj & 0x3FFFF, c = pkj >> 18;
                float4 a = __ldg(((const float4*)ob) + s * (D / 4) + lane);
                float4 r = __ldg(((const float4*)rel) + c * (D / 4) + lane);
                acc0.x = fmaf(a.x, r.x, acc0.x);
                acc0.y = fmaf(a.y, r.y, acc0.y);
                acc0.z = fmaf(a.z, r.z, acc0.z);
                acc0.w = fmaf(a.w, r.w, acc0.w);
            }
        }
        if (j < deg1) {
            int p = (s1 - s0) + j;
            int pkj = (p < 32) ? __shfl_sync(0xffffffffu, pk, p)
                               : __ldg(&g_epack[s0 + p]);
            if (lane < D / 4) {
                int s = pkj & 0x3FFFF, c = pkj >> 18;
                float4 a = __ldg(((const float4*)ob) + s * (D / 4) + lane);
                float4 r = __ldg(((const float4*)rel) + c * (D / 4) + lane);
                acc1.x = fmaf(a.x, r.x, acc1.x);
                acc1.y = fmaf(a.y, r.y, acc1.y);
                acc1.z = fmaf(a.z, r.z, acc1.z);
                acc1.w = fmaf(a.w, r.w, acc1.w);
            }
        }
    }

    if (lane < D / 4) {
        if (deg0 > 0) {
            float inv = 1.0f / (float)deg0;
            e0.x += acc0.x * inv; e0.y += acc0.y * inv;
            e0.z += acc0.z * inv; e0.w += acc0.w * inv;
        }
        ((float4*)nb)[n0 * (D / 4) + lane] = e0;
        if (deg1 > 0) {
            float inv = 1.0f / (float)deg1;
            e1.x += acc1.x * inv; e1.y += acc1.y * inv;
            e1.z += acc1.z * inv; e1.w += acc1.w * inv;
        }
        ((float4*)nb)[(n0 + 1) * (D / 4) + lane] = e1;
    }
}

// ---------------- per-step snapshot (race-free vs duplicate seeds) -----------
__global__ void k_xsnap(const float* __restrict__ ob,
                        const float* __restrict__ nb,
                        const float* __restrict__ cx,
                        const int* __restrict__ seeds) {
    int idx = blockIdx.x * blockDim.x + threadIdx.x;
    int s = idx / (D / 4), q = idx - s * (D / 4);
    if (s >= S_SEEDS) return;
    int node = seeds[s];
    float4 xv = __ldg(((const float4*)nb) + node * (D / 4) + q);
    float4 hv = __ldg(((const float4*)ob) + node * (D / 4) + q);
    ((float4*)(g_A + s * KDIM))[q] = xv;
    ((float4*)(g_A + s * KDIM + D))[q] = hv;
    float4 cv = g_cstamp[node]
        ? ((const float4*)(g_c + node * D))[q]
        : __ldg(((const float4*)cx) + node * (D / 4) + q);
    ((float4*)(g_cprev + s * D))[q] = cv;
}

// ---------------- fused LSTM GEMM + pointwise --------------------------------
// Block: 64 seeds x 16 j's x 4 gates, K processed in 2 chunks of 100 so smem
// is 54.4 KB -> 4 blocks/SM. B smem columns packed c = jj*4 + strip so a
// thread's (i,f,g,o) for one j is a single LDS.128.
__global__ void __launch_bounds__(128) k_gemmpoint(float* __restrict__ nb,
                                                   const int* __restrict__ seeds,
                                                   int t) {
    extern __shared__ float sm[];
    float* As = sm;               // [KC][LDP]
    float* Bs = sm + KC * LDP;    // [KC][LDP]
    __shared__ int sseed[64];

    int tid = threadIdx.x;
    int s0 = blockIdx.x * 64;
    int j0 = blockIdx.y * 16;

    if (tid < 64) sseed[tid] = seeds[s0 + tid];

    int tx = tid & 15;      // jj
    int ty = tid >> 4;      // seed group (8 seeds)

    float acc[8][4];
#pragma unroll
    for (int i = 0; i < 8; i++)
#pragma unroll
        for (int j = 0; j < 4; j++) acc[i][j] = 0.0f;

    for (int kc = 0; kc < 2; kc++) {
        __syncthreads();
        // A chunk: rows = seeds, k in [kc*100, kc*100+100)
        for (int i = tid; i < 64 * (KC / 4); i += 128) {
            int r = i / (KC / 4), q = i - r * (KC / 4);
            float4 v = ((const float4*)(g_A + (s0 + r) * KDIM + kc * KC))[q];
            int k = q * 4;
            As[(k + 0) * LDP + r] = v.x;
            As[(k + 1) * LDP + r] = v.y;
            As[(k + 2) * LDP + r] = v.z;
            As[(k + 3) * LDP + r] = v.w;
        }
        // B chunk: column c = jj*4 + strip holds W row (strip*100 + j0 + jj)
        for (int i = tid; i < 64 * (KC / 4); i += 128) {
            int cidx = i / (KC / 4), q = i - cidx * (KC / 4);
            int jj = cidx >> 2, strip = cidx & 3;
            int j = j0 + jj;
            float4 v = (j < D)
                ? *(const float4*)(g_W + (strip * D + j) * KDIM + kc * KC + q * 4)
                : make_float4(0.f, 0.f, 0.f, 0.f);
            int k = q * 4;
            Bs[(k + 0) * LDP + cidx] = v.x;
            Bs[(k + 1) * LDP + cidx] = v.y;
            Bs[(k + 2) * LDP + cidx] = v.z;
            Bs[(k + 3) * LDP + cidx] = v.w;
        }
        __syncthreads();

#pragma unroll 4
        for (int k = 0; k < KC; k++) {
            float4 b4 = *(const float4*)(Bs + k * LDP + tx * 4);
            float4 a0 = *(const float4*)(As + k * LDP + ty * 8);
            float4 a1 = *(const float4*)(As + k * LDP + ty * 8 + 4);
            float av[8] = {a0.x, a0.y, a0.z, a0.w, a1.x, a1.y, a1.z, a1.w};
            float bv[4] = {b4.x, b4.y, b4.z, b4.w};
#pragma unroll
            for (int i = 0; i < 8; i++)
#pragma unroll
                for (int j = 0; j < 4; j++) acc[i][j] += av[i] * bv[j];
        }
    }

    // epilogue: LSTM pointwise + scatter (duplicate-seed writes are identical)
    int j = j0 + tx;
    if (j < D) {
        float bi = __ldg(&g_b[j]);
        float bf = __ldg(&g_b[D + j]);
        float bg = __ldg(&g_b[2 * D + j]);
        float bo = __ldg(&g_b[3 * D + j]);
#pragma unroll
        for (int i = 0; i < 8; i++) {
            int sr = ty * 8 + i;
            int node = sseed[sr];
            float cp = g_cprev[(s0 + sr) * D + j];
            float ig = acc[i][0] + bi;
            float fg = acc[i][1] + bf;
            float gg = acc[i][2] + bg;
            float og = acc[i][3] + bo;
            float cn = sigf(fg) * cp + sigf(ig) * tanhf(gg);
            float hn = sigf(og) * tanhf(cn);
            g_c[node * D + j] = cn;
            nb[node * D + j] = hn;
            g_user[((t * S_SEEDS) + s0 + sr) * D + j] = hn;
        }
    }
    if (blockIdx.y == 0 && tx == 0) {
#pragma unroll
        for (int i = 0; i < 8; i++) g_cstamp[sseed[ty * 8 + i]] = 1;
    }
}

// ---------------- scoring ------------------------------------------------------
__global__ void k_score(const float* __restrict__ emb_final,
                        const int* __restrict__ cand,
                        float* __restrict__ out) {
    __shared__ float u[D];
    int n = blockIdx.x;
    int tid = threadIdx.x;
    if (tid < D) u[tid] = g_user[n * D + tid];
    __syncthreads();
    int w = tid >> 5, lane = tid & 31;
    if (w >= K_CAND) return;
    int cidx = cand[n * K_CAND + w];
    const float* cr = emb_final + cidx * D;
    float sum = 0.0f;
    for (int j = lane; j < D; j += 32) sum += u[j] * cr[j];
#pragma unroll
    for (int o = 16; o; o >>= 1) sum += __shfl_down_sync(0xffffffffu, sum, o);
    if (lane == 0) out[n * K_CAND + w] = sum;
}

// tail: restore stamp invariants for next graph replay
__global__ void k_clean(const int* __restrict__ seeds) {
    int i = blockIdx.x * blockDim.x + threadIdx.x;
    if (i < T_STEPS * S_SEEDS) g_cstamp[seeds[i]] = 0;
}

// ---------------- host ------------------------------------------------------
extern "C" void kernel_launch(void* const* d_in, const int* in_sizes, int n_in,
                              void* d_out, int out_size) {
    const float* node_emb = (const float*)d_in[0];
    const float* cx       = (const float*)d_in[1];
    const float* rel      = (const float*)d_in[2];
    const float* W_ih     = (const float*)d_in[3];
    const float* W_hh     = (const float*)d_in[4];
    const float* b_ih     = (const float*)d_in[5];
    const float* b_hh     = (const float*)d_in[6];
    const int* src   = (const int*)d_in[7];
    const int* dst   = (const int*)d_in[8];
    const int* cat   = (const int*)d_in[9];
    const int* seeds = (const int*)d_in[10];
    const int* cand  = (const int*)d_in[11];
    float* out = (float*)d_out;

    (void)in_sizes; (void)n_in; (void)out_size;

    cudaFuncSetAttribute(k_gemmpoint,
                         cudaFuncAttributeMaxDynamicSharedMemorySize, SMEM_GEMM);

    float *p_emb = nullptr, *p_emb2 = nullptr;
    cudaGetSymbolAddress((void**)&p_emb, g_emb);
    cudaGetSymbolAddress((void**)&p_emb2, g_emb2);

    // CSR build
    k_hist<<<(TE + 255) / 256, 256>>>(dst);
    k_scan<<<NBLK, 256>>>();
    k_fill<<<(TE + 255) / 256, 256>>>(src, dst, cat);

    int agg_blocks = (N_NODES / 2 + 7) / 8;
    k_agg<<<agg_blocks, 256>>>(0, node_emb, p_emb, rel);
    k_wprep<<<(G4 * KDIM + 255) / 256, 256>>>(W_ih, W_hh, b_ih, b_hh);
    k_xsnap<<<(S_SEEDS * (D / 4) + 255) / 256, 256>>>(node_emb, p_emb, cx, seeds);
    k_gemmpoint<<<dim3(S_SEEDS / 64, 7), 128, SMEM_GEMM>>>(p_emb, seeds, 0);

    for (int t = 1; t < T_STEPS; t++) {
        const float* ob = (t & 1) ? p_emb : p_emb2;
        float* nb = (t & 1) ? p_emb2 : p_emb;
        const int* seeds_t = seeds + t * S_SEEDS;
        k_agg<<<agg_blocks, 256>>>(t, ob, nb, rel);
        k_xsnap<<<(S_SEEDS * (D / 4) + 255) / 256, 256>>>(ob, nb, cx, seeds_t);
        k_gemmpoint<<<dim3(S_SEEDS / 64, 7), 128, SMEM_GEMM>>>(nb, seeds_t, t);
    }

    // final embeddings: t=15 wrote p_emb2
    k_score<<<T_STEPS * S_SEEDS, 288>>>(p_emb2, cand, out);
    k_clean<<<(T_STEPS * S_SEEDS + 255) / 256, 256>>>(seeds);
}